// round 10
// baseline (speedup 1.0000x reference)
#include <cuda_runtime.h>
#include <math.h>

#define BB 64
#define LZ 128
#define EE 512
#define HH 512
#define VV 32000
#define TT 64
#define NVBLK 500            // logits blocks (64 v each)
#define KCH 32               // k-chunk size
#define NCHUNK (EE / KCH)    // 16

typedef unsigned long long ull;

// ---------------- device scratch ----------------
__device__ float g_hT[2][HH * BB];        // hidden state, k-major [k][b], double buffered
__device__ float g_hTd[HH * BB * 2];      // GRU-output h, k-major, each value DUPLICATED: [k][2b]
__device__ float g_xT[EE * BB];           // input x, k-major [k][b]
__device__ float g_WfcT[(size_t)EE * VV]; // W_fc transposed [k][v]
__device__ float2 g_pmax[BB][NVBLK];      // per-(batch, block) partial argmax

// ---------------- helpers ----------------
__device__ __forceinline__ void fma2(ull& d, ull a, ull b) {
    asm("fma.rn.f32x2 %0, %1, %2, %0;" : "+l"(d) : "l"(a), "l"(b));
}
__device__ __forceinline__ void cp_async16(void* smem, const void* gmem) {
    unsigned s = (unsigned)__cvta_generic_to_shared(smem);
    asm volatile("cp.async.cg.shared.global [%0], [%1], 16;\n" :: "r"(s), "l"(gmem));
}
__device__ __forceinline__ void cp_commit() {
    asm volatile("cp.async.commit_group;\n");
}

// ---------------- init: h0 = z @ W_proj^T + b_proj ----------------
__global__ void init_h_kernel(const float* __restrict__ z,
                              const float* __restrict__ Wp,
                              const float* __restrict__ bp) {
    int b = threadIdx.x;
    int j = blockIdx.x * 4 + threadIdx.y;
    float acc = 0.f;
    const float* zr = z + b * LZ;
    const float* wr = Wp + j * LZ;
#pragma unroll 4
    for (int l = 0; l < LZ; l++) acc += zr[l] * wr[l];
    acc += bp[j];
    g_hT[0][j * BB + b] = acc;
    g_xT[j * BB + b]    = acc;
}

// ---------------- transpose W_fc [V][K] -> g_WfcT [K][V] ----------------
__global__ void transpose_wfc_kernel(const float* __restrict__ Wfc) {
    __shared__ float tile[32][33];
    int v0 = blockIdx.x * 32;
    int k0 = blockIdx.y * 32;
    int tx = threadIdx.x, ty = threadIdx.y;
#pragma unroll
    for (int i = ty; i < 32; i += 8)
        tile[i][tx] = Wfc[(size_t)(v0 + i) * EE + (k0 + tx)];
    __syncthreads();
#pragma unroll
    for (int i = ty; i < 32; i += 8)
        g_WfcT[(size_t)(k0 + i) * VV + (v0 + tx)] = tile[tx][i];
}

// ---------------- GRU cell, 8-way k-split ----------------
// block (32 bp, 8 ks) = 256 threads, grid 512 -> one j per block.
// Writes g_hT[1-cur] (normal layout, for next GRU) and g_hTd (duplicated, for logits).
__global__ void __launch_bounds__(256) gru_kernel(const float* __restrict__ Wih,
                                                  const float* __restrict__ bih,
                                                  const float* __restrict__ Whh,
                                                  const float* __restrict__ bhh,
                                                  int cur) {
    int bp = threadIdx.x;                 // 0..31
    int ks = threadIdx.y;                 // 0..7 (k slice of 64)
    int j  = blockIdx.x;                  // 0..511

    const float4* wri = (const float4*)(Wih + (size_t)j * EE) + ks * 16;
    const float4* wzi = (const float4*)(Wih + (size_t)(j + HH) * EE) + ks * 16;
    const float4* wni = (const float4*)(Wih + (size_t)(j + 2 * HH) * EE) + ks * 16;
    const float4* wrh = (const float4*)(Whh + (size_t)j * HH) + ks * 16;
    const float4* wzh = (const float4*)(Whh + (size_t)(j + HH) * HH) + ks * 16;
    const float4* wnh = (const float4*)(Whh + (size_t)(j + 2 * HH) * HH) + ks * 16;

    const float* xcol = g_xT + 2 * bp + (size_t)(ks * 64) * BB;
    const float* hcol = g_hT[cur] + 2 * bp + (size_t)(ks * 64) * BB;

    float air0 = 0.f, air1 = 0.f, aiz0 = 0.f, aiz1 = 0.f, ain0 = 0.f, ain1 = 0.f;
    float ahr0 = 0.f, ahr1 = 0.f, ahz0 = 0.f, ahz1 = 0.f, ahn0 = 0.f, ahn1 = 0.f;

#pragma unroll 2
    for (int k4 = 0; k4 < 16; k4++) {
        float4 wa = wri[k4], wb = wzi[k4], wc = wni[k4];
        float4 wd = wrh[k4], we = wzh[k4], wf = wnh[k4];
#pragma unroll
        for (int s = 0; s < 4; s++) {
            int k = k4 * 4 + s;
            float2 x2 = *(const float2*)(xcol + (size_t)k * BB);
            float2 h2 = *(const float2*)(hcol + (size_t)k * BB);
            float wA = ((const float*)&wa)[s];
            float wB = ((const float*)&wb)[s];
            float wC = ((const float*)&wc)[s];
            float wD = ((const float*)&wd)[s];
            float wE = ((const float*)&we)[s];
            float wF = ((const float*)&wf)[s];
            air0 += wA * x2.x; air1 += wA * x2.y;
            aiz0 += wB * x2.x; aiz1 += wB * x2.y;
            ain0 += wC * x2.x; ain1 += wC * x2.y;
            ahr0 += wD * h2.x; ahr1 += wD * h2.y;
            ahz0 += wE * h2.x; ahz1 += wE * h2.y;
            ahn0 += wF * h2.x; ahn1 += wF * h2.y;
        }
    }

    __shared__ float2 sred[8][6][32];
    sred[ks][0][bp] = make_float2(air0, air1);
    sred[ks][1][bp] = make_float2(aiz0, aiz1);
    sred[ks][2][bp] = make_float2(ain0, ain1);
    sred[ks][3][bp] = make_float2(ahr0, ahr1);
    sred[ks][4][bp] = make_float2(ahz0, ahz1);
    sred[ks][5][bp] = make_float2(ahn0, ahn1);
    __syncthreads();

    if (ks == 0) {
        float g[6][2];
#pragma unroll
        for (int gi = 0; gi < 6; gi++) {
            float a0 = 0.f, a1 = 0.f;
#pragma unroll
            for (int s = 0; s < 8; s++) {
                float2 sv = sred[s][gi][bp];
                a0 += sv.x; a1 += sv.y;
            }
            g[gi][0] = a0; g[gi][1] = a1;
        }

        float bir = bih[j], biz = bih[j + HH], bin = bih[j + 2 * HH];
        float bhr = bhh[j], bhz = bhh[j + HH], bhn = bhh[j + 2 * HH];

        float2 hprev = *(const float2*)(g_hT[cur] + (size_t)j * BB + 2 * bp);
        float* hout = g_hT[1 - cur] + (size_t)j * BB + 2 * bp;

        float h0, h1;
        {
            float r  = 1.f / (1.f + expf(-((g[0][0] + bir) + (g[3][0] + bhr))));
            float zg = 1.f / (1.f + expf(-((g[1][0] + biz) + (g[4][0] + bhz))));
            float n  = tanhf((g[2][0] + bin) + r * (g[5][0] + bhn));
            h0 = (1.f - zg) * n + zg * hprev.x;
        }
        {
            float r  = 1.f / (1.f + expf(-((g[0][1] + bir) + (g[3][1] + bhr))));
            float zg = 1.f / (1.f + expf(-((g[1][1] + biz) + (g[4][1] + bhz))));
            float n  = tanhf((g[2][1] + bin) + r * (g[5][1] + bhn));
            h1 = (1.f - zg) * n + zg * hprev.y;
        }
        hout[0] = h0;
        hout[1] = h1;
        // duplicated copy for logits: [k][2b] layout, batches 2bp,2bp+1 -> floats 4bp..4bp+3
        *(float4*)(g_hTd + (size_t)j * (2 * BB) + 4 * bp) = make_float4(h0, h0, h1, h1);
    }
}

// ---------------- logits + fused partial argmax (dup-h, zero-mov inner loop)
// grid 500 (64 v per block), block 128 = 8 vg x 16 bg, tile 8v x 4b.
// W (8KB) and duplicated-h (16KB) chunks double-buffered via cp.async.
// Per kk: 2 LDS.128 (W as (v,v+1) f32x2 pairs) + 2 LDS.128 (dup h) + 16 FFMA2.
__global__ void __launch_bounds__(128, 4) logits_kernel(const float* __restrict__ bfc,
                                                        float* __restrict__ out,
                                                        int t) {
    __shared__ __align__(16) float sW[2][KCH * 64];    // 8 KB each
    __shared__ __align__(16) float sHd[2][KCH * 128];  // 16 KB each

    int tid = threadIdx.x;
    int vg = tid & 7;          // 0..7   (8 v per thread)
    int bg = tid >> 3;         // 0..15  (4 batches per thread)
    int v0 = blockIdx.x * 64;
    int vA = v0 + vg * 8;

    auto issue_chunk = [&](int c, int buf) {
        int kc = c * KCH;
#pragma unroll
        for (int p = 0; p < 4; p++) {
            int linear = tid + p * 128;          // 0..511
            int kk = linear >> 4;
            int sub = linear & 15;
            cp_async16(&sW[buf][kk * 64 + sub * 4],
                       &g_WfcT[(size_t)(kc + kk) * VV + v0 + sub * 4]);
        }
#pragma unroll
        for (int p = 0; p < 8; p++) {
            int linear = tid + p * 128;          // 0..1023
            int kk = linear >> 5;
            int sub = linear & 31;
            cp_async16(&sHd[buf][kk * 128 + sub * 4],
                       &g_hTd[(size_t)(kc + kk) * (2 * BB) + sub * 4]);
        }
        cp_commit();
    };

    ull acc[4][4];   // [vpair][batch]
#pragma unroll
    for (int vp = 0; vp < 4; vp++)
#pragma unroll
        for (int b = 0; b < 4; b++) acc[vp][b] = 0ull;

    issue_chunk(0, 0);
    issue_chunk(1, 1);

#pragma unroll 1
    for (int c = 0; c < NCHUNK; c++) {
        if (c < NCHUNK - 1) asm volatile("cp.async.wait_group 1;\n");
        else                asm volatile("cp.async.wait_group 0;\n");
        __syncthreads();

        const float* Wb = sW[c & 1];
        const float* Hb = sHd[c & 1];

#pragma unroll
        for (int kk = 0; kk < KCH; kk++) {
            float4 w0 = *(const float4*)(Wb + kk * 64 + vg * 8);
            float4 w1 = *(const float4*)(Wb + kk * 64 + vg * 8 + 4);
            ull W01 = ((const ull*)&w0)[0];   // (vA,   vA+1)
            ull W23 = ((const ull*)&w0)[1];   // (vA+2, vA+3)
            ull W45 = ((const ull*)&w1)[0];
            ull W67 = ((const ull*)&w1)[1];
            const ulonglong2* hp = (const ulonglong2*)(Hb + kk * 128 + bg * 8);
            ulonglong2 hA = hp[0];            // batches bg*4+0, bg*4+1 (each dup'd)
            ulonglong2 hB = hp[1];            // batches bg*4+2, bg*4+3

            fma2(acc[0][0], W01, hA.x); fma2(acc[0][1], W01, hA.y);
            fma2(acc[0][2], W01, hB.x); fma2(acc[0][3], W01, hB.y);
            fma2(acc[1][0], W23, hA.x); fma2(acc[1][1], W23, hA.y);
            fma2(acc[1][2], W23, hB.x); fma2(acc[1][3], W23, hB.y);
            fma2(acc[2][0], W45, hA.x); fma2(acc[2][1], W45, hA.y);
            fma2(acc[2][2], W45, hB.x); fma2(acc[2][3], W45, hB.y);
            fma2(acc[3][0], W67, hA.x); fma2(acc[3][1], W67, hA.y);
            fma2(acc[3][2], W67, hB.x); fma2(acc[3][3], W67, hB.y);
        }

        __syncthreads();
        if (c + 2 < NCHUNK) issue_chunk(c + 2, c & 1);
    }

    float4 biasLo = *(const float4*)&bfc[vA];
    float4 biasHi = *(const float4*)&bfc[vA + 4];

#pragma unroll
    for (int i = 0; i < 4; i++) {
        int b = bg * 4 + i;
        float2 a0 = *(float2*)&acc[0][i];
        float2 a1 = *(float2*)&acc[1][i];
        float2 a2 = *(float2*)&acc[2][i];
        float2 a3 = *(float2*)&acc[3][i];

        float4 olo = make_float4(a0.x + biasLo.x, a0.y + biasLo.y,
                                 a1.x + biasLo.z, a1.y + biasLo.w);
        float4 ohi = make_float4(a2.x + biasHi.x, a2.y + biasHi.y,
                                 a3.x + biasHi.z, a3.y + biasHi.w);

        size_t rowoff = ((size_t)b * TT + t) * VV;
        __stcs((float4*)(out + rowoff + vA), olo);
        __stcs((float4*)(out + rowoff + vA + 4), ohi);

        // local argmax over 8 v (ascending, strict > keeps first-max)
        float best = olo.x; int bidx = vA;
        if (olo.y > best) { best = olo.y; bidx = vA + 1; }
        if (olo.z > best) { best = olo.z; bidx = vA + 2; }
        if (olo.w > best) { best = olo.w; bidx = vA + 3; }
        if (ohi.x > best) { best = ohi.x; bidx = vA + 4; }
        if (ohi.y > best) { best = ohi.y; bidx = vA + 5; }
        if (ohi.z > best) { best = ohi.z; bidx = vA + 6; }
        if (ohi.w > best) { best = ohi.w; bidx = vA + 7; }

        // reduce across the 8 vg lanes sharing this bg (xor bits 0..2)
#pragma unroll
        for (int m = 1; m < 8; m <<= 1) {
            float ov = __shfl_xor_sync(0xffffffffu, best, m);
            int   oi = __shfl_xor_sync(0xffffffffu, bidx, m);
            if (ov > best || (ov == best && oi < bidx)) { best = ov; bidx = oi; }
        }
        if (vg == 0)
            g_pmax[b][blockIdx.x] = make_float2(best, __int_as_float(bidx));
    }
}

// ---------------- final argmax + embedding gather ----------------
// grid 64 (one block per batch), block 128. Coalesced emb row read.
__global__ void argmax_embed_kernel(const float* __restrict__ emb) {
    int b = blockIdx.x;
    int tid = threadIdx.x;

    float best = -3.4e38f;
    int bidx = 0x7fffffff;
    for (int i = tid; i < NVBLK; i += 128) {
        float2 p = g_pmax[b][i];
        float v = p.x;
        int idx = __float_as_int(p.y);
        if (v > best || (v == best && idx < bidx)) { best = v; bidx = idx; }
    }

    __shared__ float sv[128];
    __shared__ int   si[128];
    sv[tid] = best; si[tid] = bidx;
    __syncthreads();
#pragma unroll
    for (int s = 64; s > 0; s >>= 1) {
        if (tid < s) {
            float ov = sv[tid + s]; int oi = si[tid + s];
            if (ov > sv[tid] || (ov == sv[tid] && oi < si[tid])) { sv[tid] = ov; si[tid] = oi; }
        }
        __syncthreads();
    }
    int id = si[0];

    const float* er = emb + (size_t)id * EE;
    for (int k = tid; k < EE; k += 128) g_xT[(size_t)k * BB + b] = er[k];
}

// ---------------- launch ----------------
extern "C" void kernel_launch(void* const* d_in, const int* in_sizes, int n_in,
                              void* d_out, int out_size) {
    const float* z     = (const float*)d_in[0];
    const float* emb   = (const float*)d_in[1];
    const float* Wproj = (const float*)d_in[2];
    const float* bproj = (const float*)d_in[3];
    const float* Wih   = (const float*)d_in[4];
    const float* bih   = (const float*)d_in[5];
    const float* Whh   = (const float*)d_in[6];
    const float* bhh   = (const float*)d_in[7];
    const float* Wfc   = (const float*)d_in[8];
    const float* bfc   = (const float*)d_in[9];
    float* out = (float*)d_out;

    init_h_kernel<<<128, dim3(64, 4)>>>(z, Wproj, bproj);
    transpose_wfc_kernel<<<dim3(VV / 32, EE / 32), dim3(32, 8)>>>(Wfc);

    int cur = 0;
    for (int t = 0; t < TT; t++) {
        gru_kernel<<<512, dim3(32, 8)>>>(Wih, bih, Whh, bhh, cur);
        logits_kernel<<<NVBLK, 128>>>(bfc, out, t);
        argmax_embed_kernel<<<64, 128>>>(emb);
        cur = 1 - cur;
    }
}

// round 11
// speedup vs baseline: 1.6149x; 1.6149x over previous
#include <cuda_runtime.h>
#include <math.h>

#define BB 64
#define LZ 128
#define EE 512
#define HH 512
#define VV 32000
#define TT 64
#define NVBLK 1000           // logits blocks (32 v each)
#define KCH 32               // k-chunk size
#define NCHUNK (EE / KCH)    // 16

typedef unsigned long long ull;

// ---------------- device scratch ----------------
__device__ float g_hT[2][HH * BB];        // hidden state, k-major [k][b], double buffered
__device__ float g_xT[EE * BB];           // input x, k-major [k][b]
__device__ float g_WfcT[(size_t)EE * VV]; // W_fc transposed [k][v]
__device__ float2 g_pmax[BB][NVBLK];      // per-(batch, block) partial argmax

// ---------------- helpers ----------------
__device__ __forceinline__ void fma2(ull& d, ull a, ull b) {
    asm("fma.rn.f32x2 %0, %1, %2, %0;" : "+l"(d) : "l"(a), "l"(b));
}
__device__ __forceinline__ ull dup2(float a) {
    ull r;
    asm("mov.b64 %0, {%1, %2};" : "=l"(r) : "f"(a), "f"(a));
    return r;
}
__device__ __forceinline__ void cp_async16(void* smem, const void* gmem) {
    unsigned s = (unsigned)__cvta_generic_to_shared(smem);
    asm volatile("cp.async.cg.shared.global [%0], [%1], 16;\n" :: "r"(s), "l"(gmem));
}
__device__ __forceinline__ void cp_commit() {
    asm volatile("cp.async.commit_group;\n");
}

// ---------------- init: h0 = z @ W_proj^T + b_proj ----------------
__global__ void init_h_kernel(const float* __restrict__ z,
                              const float* __restrict__ Wp,
                              const float* __restrict__ bp) {
    int b = threadIdx.x;
    int j = blockIdx.x * 4 + threadIdx.y;
    float acc = 0.f;
    const float* zr = z + b * LZ;
    const float* wr = Wp + j * LZ;
#pragma unroll 4
    for (int l = 0; l < LZ; l++) acc += zr[l] * wr[l];
    acc += bp[j];
    g_hT[0][j * BB + b] = acc;
    g_xT[j * BB + b]    = acc;
}

// ---------------- transpose W_fc [V][K] -> g_WfcT [K][V] ----------------
__global__ void transpose_wfc_kernel(const float* __restrict__ Wfc) {
    __shared__ float tile[32][33];
    int v0 = blockIdx.x * 32;
    int k0 = blockIdx.y * 32;
    int tx = threadIdx.x, ty = threadIdx.y;
#pragma unroll
    for (int i = ty; i < 32; i += 8)
        tile[i][tx] = Wfc[(size_t)(v0 + i) * EE + (k0 + tx)];
    __syncthreads();
#pragma unroll
    for (int i = ty; i < 32; i += 8)
        g_WfcT[(size_t)(k0 + i) * VV + (v0 + tx)] = tile[tx][i];
}

// ---------------- GRU cell, 8-way k-split ----------------
// block (32 bp, 8 ks) = 256 threads, grid 512 -> one j per block
__global__ void __launch_bounds__(256) gru_kernel(const float* __restrict__ Wih,
                                                  const float* __restrict__ bih,
                                                  const float* __restrict__ Whh,
                                                  const float* __restrict__ bhh,
                                                  int cur) {
    int bp = threadIdx.x;                 // 0..31
    int ks = threadIdx.y;                 // 0..7 (k slice of 64)
    int j  = blockIdx.x;                  // 0..511

    const float4* wri = (const float4*)(Wih + (size_t)j * EE) + ks * 16;
    const float4* wzi = (const float4*)(Wih + (size_t)(j + HH) * EE) + ks * 16;
    const float4* wni = (const float4*)(Wih + (size_t)(j + 2 * HH) * EE) + ks * 16;
    const float4* wrh = (const float4*)(Whh + (size_t)j * HH) + ks * 16;
    const float4* wzh = (const float4*)(Whh + (size_t)(j + HH) * HH) + ks * 16;
    const float4* wnh = (const float4*)(Whh + (size_t)(j + 2 * HH) * HH) + ks * 16;

    const float* xcol = g_xT + 2 * bp + (size_t)(ks * 64) * BB;
    const float* hcol = g_hT[cur] + 2 * bp + (size_t)(ks * 64) * BB;

    float air0 = 0.f, air1 = 0.f, aiz0 = 0.f, aiz1 = 0.f, ain0 = 0.f, ain1 = 0.f;
    float ahr0 = 0.f, ahr1 = 0.f, ahz0 = 0.f, ahz1 = 0.f, ahn0 = 0.f, ahn1 = 0.f;

#pragma unroll 2
    for (int k4 = 0; k4 < 16; k4++) {
        float4 wa = wri[k4], wb = wzi[k4], wc = wni[k4];
        float4 wd = wrh[k4], we = wzh[k4], wf = wnh[k4];
#pragma unroll
        for (int s = 0; s < 4; s++) {
            int k = k4 * 4 + s;
            float2 x2 = *(const float2*)(xcol + (size_t)k * BB);
            float2 h2 = *(const float2*)(hcol + (size_t)k * BB);
            float wA = ((const float*)&wa)[s];
            float wB = ((const float*)&wb)[s];
            float wC = ((const float*)&wc)[s];
            float wD = ((const float*)&wd)[s];
            float wE = ((const float*)&we)[s];
            float wF = ((const float*)&wf)[s];
            air0 += wA * x2.x; air1 += wA * x2.y;
            aiz0 += wB * x2.x; aiz1 += wB * x2.y;
            ain0 += wC * x2.x; ain1 += wC * x2.y;
            ahr0 += wD * h2.x; ahr1 += wD * h2.y;
            ahz0 += wE * h2.x; ahz1 += wE * h2.y;
            ahn0 += wF * h2.x; ahn1 += wF * h2.y;
        }
    }

    __shared__ float2 sred[8][6][32];
    sred[ks][0][bp] = make_float2(air0, air1);
    sred[ks][1][bp] = make_float2(aiz0, aiz1);
    sred[ks][2][bp] = make_float2(ain0, ain1);
    sred[ks][3][bp] = make_float2(ahr0, ahr1);
    sred[ks][4][bp] = make_float2(ahz0, ahz1);
    sred[ks][5][bp] = make_float2(ahn0, ahn1);
    __syncthreads();

    if (ks == 0) {
        float g[6][2];
#pragma unroll
        for (int gi = 0; gi < 6; gi++) {
            float a0 = 0.f, a1 = 0.f;
#pragma unroll
            for (int s = 0; s < 8; s++) {
                float2 sv = sred[s][gi][bp];
                a0 += sv.x; a1 += sv.y;
            }
            g[gi][0] = a0; g[gi][1] = a1;
        }

        float bir = bih[j], biz = bih[j + HH], bin = bih[j + 2 * HH];
        float bhr = bhh[j], bhz = bhh[j + HH], bhn = bhh[j + 2 * HH];

        float2 hprev = *(const float2*)(g_hT[cur] + (size_t)j * BB + 2 * bp);
        float* hout = g_hT[1 - cur] + (size_t)j * BB + 2 * bp;

        {
            float r  = 1.f / (1.f + expf(-((g[0][0] + bir) + (g[3][0] + bhr))));
            float zg = 1.f / (1.f + expf(-((g[1][0] + biz) + (g[4][0] + bhz))));
            float n  = tanhf((g[2][0] + bin) + r * (g[5][0] + bhn));
            hout[0]  = (1.f - zg) * n + zg * hprev.x;
        }
        {
            float r  = 1.f / (1.f + expf(-((g[0][1] + bir) + (g[3][1] + bhr))));
            float zg = 1.f / (1.f + expf(-((g[1][1] + biz) + (g[4][1] + bhz))));
            float n  = tanhf((g[2][1] + bin) + r * (g[5][1] + bhn));
            hout[1]  = (1.f - zg) * n + zg * hprev.y;
        }
    }
}

// ---------------- logits + fused partial argmax (cp.async pipelined) -------
// grid 1000 (32 v per block), block 64 = 8 vg x 8 bg, tile 4v x 8b.
// Same per-thread code as the proven 48.7us config; smaller blocks give
// near-perfect wave balance (max 7 blocks/SM vs avg 6.76).
__global__ void __launch_bounds__(64) logits_kernel(const float* __restrict__ bfc,
                                                    float* __restrict__ out,
                                                    int t, int hbuf) {
    __shared__ __align__(16) float sW[2][KCH * 32];  // 4 KB each
    __shared__ __align__(16) float sH[2][KCH * 64];  // 8 KB each

    int tid = threadIdx.x;          // 0..63
    int vg = tid & 7;               // 0..7
    int bg = tid >> 3;              // 0..7
    int v0 = blockIdx.x * 32;
    int vA = v0 + vg * 4;

    const float* hbase = g_hT[hbuf];

    auto issue_chunk = [&](int c, int buf) {
        int kc = c * KCH;
#pragma unroll
        for (int p = 0; p < 4; p++) {
            int linear = tid + p * 64;           // 0..255
            int kk = linear >> 3;
            int sub = linear & 7;
            cp_async16(&sW[buf][kk * 32 + sub * 4],
                       &g_WfcT[(size_t)(kc + kk) * VV + v0 + sub * 4]);
        }
#pragma unroll
        for (int p = 0; p < 8; p++) {
            int linear = tid + p * 64;           // 0..511
            int kk = linear >> 4;
            int sub = linear & 15;
            cp_async16(&sH[buf][kk * 64 + sub * 4],
                       &hbase[(size_t)(kc + kk) * BB + sub * 4]);
        }
        cp_commit();
    };

    ull acc[4][4];
#pragma unroll
    for (int v = 0; v < 4; v++)
#pragma unroll
        for (int p = 0; p < 4; p++) acc[v][p] = 0ull;

    issue_chunk(0, 0);
    issue_chunk(1, 1);

#pragma unroll 1
    for (int c = 0; c < NCHUNK; c++) {
        if (c < NCHUNK - 1) asm volatile("cp.async.wait_group 1;\n");
        else                asm volatile("cp.async.wait_group 0;\n");
        __syncthreads();

        const float* Wb = sW[c & 1];
        const float* Hb = sH[c & 1];

#pragma unroll
        for (int kk = 0; kk < KCH; kk++) {
            float4 w = *(const float4*)(Wb + kk * 32 + vg * 4);
            ulonglong2 h01 = *(const ulonglong2*)(Hb + kk * 64 + bg * 8);
            ulonglong2 h23 = *(const ulonglong2*)(Hb + kk * 64 + bg * 8 + 4);

            ull W0 = dup2(w.x), W1 = dup2(w.y), W2 = dup2(w.z), W3 = dup2(w.w);
            fma2(acc[0][0], W0, h01.x); fma2(acc[0][1], W0, h01.y);
            fma2(acc[0][2], W0, h23.x); fma2(acc[0][3], W0, h23.y);
            fma2(acc[1][0], W1, h01.x); fma2(acc[1][1], W1, h01.y);
            fma2(acc[1][2], W1, h23.x); fma2(acc[1][3], W1, h23.y);
            fma2(acc[2][0], W2, h01.x); fma2(acc[2][1], W2, h01.y);
            fma2(acc[2][2], W2, h23.x); fma2(acc[2][3], W2, h23.y);
            fma2(acc[3][0], W3, h01.x); fma2(acc[3][1], W3, h01.y);
            fma2(acc[3][2], W3, h23.x); fma2(acc[3][3], W3, h23.y);
        }

        __syncthreads();                 // everyone done with buffer (c&1)
        if (c + 2 < NCHUNK) issue_chunk(c + 2, c & 1);
    }

    float4 bias = *(const float4*)&bfc[vA];

#pragma unroll
    for (int i = 0; i < 8; i++) {
        int b = bg * 8 + i;
        int p = i >> 1, cc = i & 1;

        float4 o;
        o.x = ((const float*)&acc[0][p])[cc] + bias.x;
        o.y = ((const float*)&acc[1][p])[cc] + bias.y;
        o.z = ((const float*)&acc[2][p])[cc] + bias.z;
        o.w = ((const float*)&acc[3][p])[cc] + bias.w;

        size_t rowoff = ((size_t)b * TT + t) * VV;
        __stcs((float4*)(out + rowoff + vA), o);

        float best = o.x; int bidx = vA;
        if (o.y > best) { best = o.y; bidx = vA + 1; }
        if (o.z > best) { best = o.z; bidx = vA + 2; }
        if (o.w > best) { best = o.w; bidx = vA + 3; }

        // reduce across the 8 vg lanes sharing this bg (lane bits 0..2)
#pragma unroll
        for (int m = 1; m < 8; m <<= 1) {
            float ov = __shfl_xor_sync(0xffffffffu, best, m);
            int   oi = __shfl_xor_sync(0xffffffffu, bidx, m);
            if (ov > best || (ov == best && oi < bidx)) { best = ov; bidx = oi; }
        }
        if (vg == 0)
            g_pmax[b][blockIdx.x] = make_float2(best, __int_as_float(bidx));
    }
}

// ---------------- final argmax + embedding gather ----------------
// grid 64 (one block per batch), block 128. Coalesced emb row read.
__global__ void argmax_embed_kernel(const float* __restrict__ emb) {
    int b = blockIdx.x;
    int tid = threadIdx.x;

    float best = -3.4e38f;
    int bidx = 0x7fffffff;
    for (int i = tid; i < NVBLK; i += 128) {
        float2 p = g_pmax[b][i];
        float v = p.x;
        int idx = __float_as_int(p.y);
        if (v > best || (v == best && idx < bidx)) { best = v; bidx = idx; }
    }

    __shared__ float sv[128];
    __shared__ int   si[128];
    sv[tid] = best; si[tid] = bidx;
    __syncthreads();
#pragma unroll
    for (int s = 64; s > 0; s >>= 1) {
        if (tid < s) {
            float ov = sv[tid + s]; int oi = si[tid + s];
            if (ov > sv[tid] || (ov == sv[tid] && oi < si[tid])) { sv[tid] = ov; si[tid] = oi; }
        }
        __syncthreads();
    }
    int id = si[0];

    const float* er = emb + (size_t)id * EE;
    for (int k = tid; k < EE; k += 128) g_xT[(size_t)k * BB + b] = er[k];
}

// ---------------- launch ----------------
extern "C" void kernel_launch(void* const* d_in, const int* in_sizes, int n_in,
                              void* d_out, int out_size) {
    const float* z     = (const float*)d_in[0];
    const float* emb   = (const float*)d_in[1];
    const float* Wproj = (const float*)d_in[2];
    const float* bproj = (const float*)d_in[3];
    const float* Wih   = (const float*)d_in[4];
    const float* bih   = (const float*)d_in[5];
    const float* Whh   = (const float*)d_in[6];
    const float* bhh   = (const float*)d_in[7];
    const float* Wfc   = (const float*)d_in[8];
    const float* bfc   = (const float*)d_in[9];
    float* out = (float*)d_out;

    init_h_kernel<<<128, dim3(64, 4)>>>(z, Wproj, bproj);
    transpose_wfc_kernel<<<dim3(VV / 32, EE / 32), dim3(32, 8)>>>(Wfc);

    int cur = 0;
    for (int t = 0; t < TT; t++) {
        gru_kernel<<<512, dim3(32, 8)>>>(Wih, bih, Whh, bhh, cur);
        logits_kernel<<<NVBLK, 64>>>(bfc, out, t, 1 - cur);
        argmax_embed_kernel<<<64, 128>>>(emb);
        cur = 1 - cur;
    }
}

// round 13
// speedup vs baseline: 1.8939x; 1.1728x over previous
#include <cuda_runtime.h>
#include <cuda_bf16.h>
#include <math.h>

#define BB 64
#define LZ 128
#define EE 512
#define HH 512
#define VV 32000
#define TT 64
#define NVBLK 500            // logits blocks (64 v each)
#define KCH 32               // k-chunk size (elements)
#define NCHUNK (EE / KCH)    // 16

typedef unsigned long long ull;
typedef unsigned int u32;

// ---------------- device scratch ----------------
__device__ float g_hT[2][HH * BB];                 // hidden, k-major [k][b], double buffered
__device__ float g_xT[EE * BB];                    // GRU input x, k-major [k][b]
__device__ __align__(16) __nv_bfloat16 g_Whib[(size_t)VV * EE];  // W_fc bf16-hi [v][k]
__device__ __align__(16) __nv_bfloat16 g_Wlob[(size_t)VV * EE];  // W_fc bf16-lo [v][k]
__device__ __align__(16) __nv_bfloat16 g_hbhi[BB * HH];          // h bf16-hi, b-major [b][k]
__device__ __align__(16) __nv_bfloat16 g_hblo[BB * HH];          // h bf16-lo, b-major [b][k]
__device__ float2 g_pmax[BB][NVBLK];               // per-(batch, block) partial argmax

// ---------------- helpers ----------------
__device__ __forceinline__ void cp_async16(void* smem, const void* gmem) {
    u32 s = (u32)__cvta_generic_to_shared(smem);
    asm volatile("cp.async.cg.shared.global [%0], [%1], 16;\n" :: "r"(s), "l"(gmem));
}
__device__ __forceinline__ void cp_commit() {
    asm volatile("cp.async.commit_group;\n");
}
__device__ __forceinline__ void mma_bf16(float* c, const u32* a, u32 b0, u32 b1) {
    asm volatile(
        "mma.sync.aligned.m16n8k16.row.col.f32.bf16.bf16.f32 "
        "{%0,%1,%2,%3}, {%4,%5,%6,%7}, {%8,%9}, {%0,%1,%2,%3};"
        : "+f"(c[0]), "+f"(c[1]), "+f"(c[2]), "+f"(c[3])
        : "r"(a[0]), "r"(a[1]), "r"(a[2]), "r"(a[3]), "r"(b0), "r"(b1));
}

// ---------------- init: h0 = z @ W_proj^T + b_proj ----------------
__global__ void init_h_kernel(const float* __restrict__ z,
                              const float* __restrict__ Wp,
                              const float* __restrict__ bp) {
    int b = threadIdx.x;
    int j = blockIdx.x * 4 + threadIdx.y;
    float acc = 0.f;
    const float* zr = z + b * LZ;
    const float* wr = Wp + j * LZ;
#pragma unroll 4
    for (int l = 0; l < LZ; l++) acc += zr[l] * wr[l];
    acc += bp[j];
    g_hT[0][j * BB + b] = acc;
    g_xT[j * BB + b]    = acc;
}

// ---------------- split W_fc into bf16 hi/lo (once) ----------------
__global__ void split_wfc_kernel(const float* __restrict__ Wfc) {
    size_t i = ((size_t)blockIdx.x * 256 + threadIdx.x) * 4;
    float4 w = *(const float4*)(Wfc + i);
    __nv_bfloat16 h0 = __float2bfloat16(w.x);
    __nv_bfloat16 h1 = __float2bfloat16(w.y);
    __nv_bfloat16 h2 = __float2bfloat16(w.z);
    __nv_bfloat16 h3 = __float2bfloat16(w.w);
    __nv_bfloat16 l0 = __float2bfloat16(w.x - __bfloat162float(h0));
    __nv_bfloat16 l1 = __float2bfloat16(w.y - __bfloat162float(h1));
    __nv_bfloat16 l2 = __float2bfloat16(w.z - __bfloat162float(h2));
    __nv_bfloat16 l3 = __float2bfloat16(w.w - __bfloat162float(h3));
    *(__nv_bfloat162*)(g_Whib + i)     = __nv_bfloat162(h0, h1);
    *(__nv_bfloat162*)(g_Whib + i + 2) = __nv_bfloat162(h2, h3);
    *(__nv_bfloat162*)(g_Wlob + i)     = __nv_bfloat162(l0, l1);
    *(__nv_bfloat162*)(g_Wlob + i + 2) = __nv_bfloat162(l2, l3);
}

// ---------------- GRU cell, 8-way k-split ----------------
// block (32 bp, 8 ks) = 256 threads, grid 512 -> one j per block.
// Writes g_hT[1-cur] and bf16 hi/lo b-major copies for MMA logits.
__global__ void __launch_bounds__(256) gru_kernel(const float* __restrict__ Wih,
                                                  const float* __restrict__ bih,
                                                  const float* __restrict__ Whh,
                                                  const float* __restrict__ bhh,
                                                  int cur) {
    int bp = threadIdx.x;
    int ks = threadIdx.y;
    int j  = blockIdx.x;

    const float4* wri = (const float4*)(Wih + (size_t)j * EE) + ks * 16;
    const float4* wzi = (const float4*)(Wih + (size_t)(j + HH) * EE) + ks * 16;
    const float4* wni = (const float4*)(Wih + (size_t)(j + 2 * HH) * EE) + ks * 16;
    const float4* wrh = (const float4*)(Whh + (size_t)j * HH) + ks * 16;
    const float4* wzh = (const float4*)(Whh + (size_t)(j + HH) * HH) + ks * 16;
    const float4* wnh = (const float4*)(Whh + (size_t)(j + 2 * HH) * HH) + ks * 16;

    const float* xcol = g_xT + 2 * bp + (size_t)(ks * 64) * BB;
    const float* hcol = g_hT[cur] + 2 * bp + (size_t)(ks * 64) * BB;

    float air0 = 0.f, air1 = 0.f, aiz0 = 0.f, aiz1 = 0.f, ain0 = 0.f, ain1 = 0.f;
    float ahr0 = 0.f, ahr1 = 0.f, ahz0 = 0.f, ahz1 = 0.f, ahn0 = 0.f, ahn1 = 0.f;

#pragma unroll 2
    for (int k4 = 0; k4 < 16; k4++) {
        float4 wa = wri[k4], wb = wzi[k4], wc = wni[k4];
        float4 wd = wrh[k4], we = wzh[k4], wf = wnh[k4];
#pragma unroll
        for (int s = 0; s < 4; s++) {
            int k = k4 * 4 + s;
            float2 x2 = *(const float2*)(xcol + (size_t)k * BB);
            float2 h2 = *(const float2*)(hcol + (size_t)k * BB);
            float wA = ((const float*)&wa)[s];
            float wB = ((const float*)&wb)[s];
            float wC = ((const float*)&wc)[s];
            float wD = ((const float*)&wd)[s];
            float wE = ((const float*)&we)[s];
            float wF = ((const float*)&wf)[s];
            air0 += wA * x2.x; air1 += wA * x2.y;
            aiz0 += wB * x2.x; aiz1 += wB * x2.y;
            ain0 += wC * x2.x; ain1 += wC * x2.y;
            ahr0 += wD * h2.x; ahr1 += wD * h2.y;
            ahz0 += wE * h2.x; ahz1 += wE * h2.y;
            ahn0 += wF * h2.x; ahn1 += wF * h2.y;
        }
    }

    __shared__ float2 sred[8][6][32];
    sred[ks][0][bp] = make_float2(air0, air1);
    sred[ks][1][bp] = make_float2(aiz0, aiz1);
    sred[ks][2][bp] = make_float2(ain0, ain1);
    sred[ks][3][bp] = make_float2(ahr0, ahr1);
    sred[ks][4][bp] = make_float2(ahz0, ahz1);
    sred[ks][5][bp] = make_float2(ahn0, ahn1);
    __syncthreads();

    if (ks == 0) {
        float g[6][2];
#pragma unroll
        for (int gi = 0; gi < 6; gi++) {
            float a0 = 0.f, a1 = 0.f;
#pragma unroll
            for (int s = 0; s < 8; s++) {
                float2 sv = sred[s][gi][bp];
                a0 += sv.x; a1 += sv.y;
            }
            g[gi][0] = a0; g[gi][1] = a1;
        }

        float bir = bih[j], biz = bih[j + HH], bin = bih[j + 2 * HH];
        float bhr = bhh[j], bhz = bhh[j + HH], bhn = bhh[j + 2 * HH];

        float2 hprev = *(const float2*)(g_hT[cur] + (size_t)j * BB + 2 * bp);
        float* hout = g_hT[1 - cur] + (size_t)j * BB + 2 * bp;

        float h0, h1;
        {
            float r  = 1.f / (1.f + expf(-((g[0][0] + bir) + (g[3][0] + bhr))));
            float zg = 1.f / (1.f + expf(-((g[1][0] + biz) + (g[4][0] + bhz))));
            float n  = tanhf((g[2][0] + bin) + r * (g[5][0] + bhn));
            h0 = (1.f - zg) * n + zg * hprev.x;
        }
        {
            float r  = 1.f / (1.f + expf(-((g[0][1] + bir) + (g[3][1] + bhr))));
            float zg = 1.f / (1.f + expf(-((g[1][1] + biz) + (g[4][1] + bhz))));
            float n  = tanhf((g[2][1] + bin) + r * (g[5][1] + bhn));
            h1 = (1.f - zg) * n + zg * hprev.y;
        }
        hout[0] = h0;
        hout[1] = h1;

        __nv_bfloat16 h0h = __float2bfloat16(h0);
        __nv_bfloat16 h1h = __float2bfloat16(h1);
        g_hbhi[(size_t)(2 * bp)     * HH + j] = h0h;
        g_hbhi[(size_t)(2 * bp + 1) * HH + j] = h1h;
        g_hblo[(size_t)(2 * bp)     * HH + j] = __float2bfloat16(h0 - __bfloat162float(h0h));
        g_hblo[(size_t)(2 * bp + 1) * HH + j] = __float2bfloat16(h1 - __bfloat162float(h1h));
    }
}

// ---------------- logits via bf16 3-term-split mma.sync ----------------
// grid 500 (64 v per block), block 128 (4 warps; warp w owns v rows w*16..+15).
// k-chunks of 32, double-buffered cp.async (R7 skeleton). Smem rows padded to
// 80B -> conflict-free fragment loads. D kept in fp32 accumulators, staged to
// smem for the proven coalesced store + fused argmax epilogue.
// smem layout (bytes): Whi[2]@0/5120, Wlo[2]@10240/15360, Bhi[2]@20480/25600,
// Blo[2]@30720/35840; total 40960. sD (64x66 fp32) aliases offset 0 after loop.
#define LROW 80
#define SMEM_DYN 40960

__global__ void __launch_bounds__(128) logits_kernel(const float* __restrict__ bfc,
                                                     float* __restrict__ out,
                                                     int t) {
    extern __shared__ __align__(16) char smem[];
    int tid = threadIdx.x;
    int w = tid >> 5;
    int lane = tid & 31;
    int g = lane >> 2;          // groupID
    int qk = lane & 3;          // thread-in-group
    int v0 = blockIdx.x * 64;

    const int OWHI[2] = {0, 5120};
    const int OWLO[2] = {10240, 15360};
    const int OBHI[2] = {20480, 25600};
    const int OBLO[2] = {30720, 35840};

    auto issue_chunk = [&](int c, int buf) {
        int kc = c * KCH;
#pragma unroll
        for (int p = 0; p < 2; p++) {
            int lin = tid + p * 128;            // 0..255
            int row = lin >> 2, seg = lin & 3;
            cp_async16(smem + OWHI[buf] + row * LROW + seg * 16,
                       g_Whib + (size_t)(v0 + row) * EE + kc + seg * 8);
            cp_async16(smem + OWLO[buf] + row * LROW + seg * 16,
                       g_Wlob + (size_t)(v0 + row) * EE + kc + seg * 8);
            cp_async16(smem + OBHI[buf] + row * LROW + seg * 16,
                       g_hbhi + (size_t)row * HH + kc + seg * 8);
            cp_async16(smem + OBLO[buf] + row * LROW + seg * 16,
                       g_hblo + (size_t)row * HH + kc + seg * 8);
        }
        cp_commit();
    };

    float acc[8][4];
#pragma unroll
    for (int n = 0; n < 8; n++)
#pragma unroll
        for (int i = 0; i < 4; i++) acc[n][i] = 0.f;

    issue_chunk(0, 0);
    issue_chunk(1, 1);

#pragma unroll 1
    for (int c = 0; c < NCHUNK; c++) {
        if (c < NCHUNK - 1) asm volatile("cp.async.wait_group 1;\n");
        else                asm volatile("cp.async.wait_group 0;\n");
        __syncthreads();

        const char* Wh = smem + OWHI[c & 1];
        const char* Wl = smem + OWLO[c & 1];
        const char* Bh = smem + OBHI[c & 1];
        const char* Bl = smem + OBLO[c & 1];

#pragma unroll
        for (int ks = 0; ks < 2; ks++) {
            int ko = ks * 32;                       // byte offset for 16 k
            u32 abase = (u32)((w * 16 + g) * LROW + ko + qk * 4);
            u32 ahi[4], alo[4];
            ahi[0] = *(const u32*)(Wh + abase);
            ahi[1] = *(const u32*)(Wh + abase + 8 * LROW);
            ahi[2] = *(const u32*)(Wh + abase + 16);
            ahi[3] = *(const u32*)(Wh + abase + 8 * LROW + 16);
            alo[0] = *(const u32*)(Wl + abase);
            alo[1] = *(const u32*)(Wl + abase + 8 * LROW);
            alo[2] = *(const u32*)(Wl + abase + 16);
            alo[3] = *(const u32*)(Wl + abase + 8 * LROW + 16);

#pragma unroll
            for (int n = 0; n < 8; n++) {
                u32 bbase = (u32)((n * 8 + g) * LROW + ko + qk * 4);
                u32 bhi0 = *(const u32*)(Bh + bbase);
                u32 bhi1 = *(const u32*)(Bh + bbase + 16);
                u32 blo0 = *(const u32*)(Bl + bbase);
                u32 blo1 = *(const u32*)(Bl + bbase + 16);
                mma_bf16(acc[n], ahi, bhi0, bhi1);
                mma_bf16(acc[n], ahi, blo0, blo1);
                mma_bf16(acc[n], alo, bhi0, bhi1);
            }
        }

        __syncthreads();
        if (c + 2 < NCHUNK) issue_chunk(c + 2, c & 1);
    }

    // stage D to smem [64v][66 fp32] (aliases stage buffers; all compute done)
    __syncthreads();
    float* sD = (float*)smem;
#pragma unroll
    for (int n = 0; n < 8; n++) {
        int b = n * 8 + qk * 2;
        int v = w * 16 + g;
        *(float2*)(sD + v * 66 + b)       = make_float2(acc[n][0], acc[n][1]);
        *(float2*)(sD + (v + 8) * 66 + b) = make_float2(acc[n][2], acc[n][3]);
    }
    __syncthreads();

    // output + fused partial argmax (R4/R7 pattern): vg 4v, bg 8b per thread
    int vg = tid & 15;
    int bg = tid >> 4;
    int vA = v0 + vg * 4;
    float4 bias = *(const float4*)&bfc[vA];

#pragma unroll
    for (int i = 0; i < 8; i++) {
        int b = bg * 8 + i;
        float4 o;
        o.x = sD[(vg * 4 + 0) * 66 + b] + bias.x;
        o.y = sD[(vg * 4 + 1) * 66 + b] + bias.y;
        o.z = sD[(vg * 4 + 2) * 66 + b] + bias.z;
        o.w = sD[(vg * 4 + 3) * 66 + b] + bias.w;

        size_t rowoff = ((size_t)b * TT + t) * VV;
        __stcs((float4*)(out + rowoff + vA), o);

        float best = o.x; int bidx = vA;
        if (o.y > best) { best = o.y; bidx = vA + 1; }
        if (o.z > best) { best = o.z; bidx = vA + 2; }
        if (o.w > best) { best = o.w; bidx = vA + 3; }

#pragma unroll
        for (int m = 1; m < 16; m <<= 1) {
            float ov = __shfl_xor_sync(0xffffffffu, best, m);
            int   oi = __shfl_xor_sync(0xffffffffu, bidx, m);
            if (ov > best || (ov == best && oi < bidx)) { best = ov; bidx = oi; }
        }
        if (vg == 0)
            g_pmax[b][blockIdx.x] = make_float2(best, __int_as_float(bidx));
    }
}

// ---------------- final argmax + embedding gather ----------------
__global__ void argmax_embed_kernel(const float* __restrict__ emb) {
    int b = blockIdx.x;
    int tid = threadIdx.x;

    float best = -3.4e38f;
    int bidx = 0x7fffffff;
    for (int i = tid; i < NVBLK; i += 128) {
        float2 p = g_pmax[b][i];
        float v = p.x;
        int idx = __float_as_int(p.y);
        if (v > best || (v == best && idx < bidx)) { best = v; bidx = idx; }
    }

    __shared__ float sv[128];
    __shared__ int   si[128];
    sv[tid] = best; si[tid] = bidx;
    __syncthreads();
#pragma unroll
    for (int s = 64; s > 0; s >>= 1) {
        if (tid < s) {
            float ov = sv[tid + s]; int oi = si[tid + s];
            if (ov > sv[tid] || (ov == sv[tid] && oi < si[tid])) { sv[tid] = ov; si[tid] = oi; }
        }
        __syncthreads();
    }
    int id = si[0];

    const float* er = emb + (size_t)id * EE;
    for (int k = tid; k < EE; k += 128) g_xT[(size_t)k * BB + b] = er[k];
}

// ---------------- launch ----------------
extern "C" void kernel_launch(void* const* d_in, const int* in_sizes, int n_in,
                              void* d_out, int out_size) {
    const float* z     = (const float*)d_in[0];
    const float* emb   = (const float*)d_in[1];
    const float* Wproj = (const float*)d_in[2];
    const float* bproj = (const float*)d_in[3];
    const float* Wih   = (const float*)d_in[4];
    const float* bih   = (const float*)d_in[5];
    const float* Whh   = (const float*)d_in[6];
    const float* bhh   = (const float*)d_in[7];
    const float* Wfc   = (const float*)d_in[8];
    const float* bfc   = (const float*)d_in[9];
    float* out = (float*)d_out;

    cudaFuncSetAttribute(logits_kernel,
                         cudaFuncAttributeMaxDynamicSharedMemorySize, SMEM_DYN);

    init_h_kernel<<<128, dim3(64, 4)>>>(z, Wproj, bproj);
    split_wfc_kernel<<<(int)(((size_t)VV * EE / 4) / 256), 256>>>(Wfc);

    int cur = 0;
    for (int t = 0; t < TT; t++) {
        gru_kernel<<<512, dim3(32, 8)>>>(Wih, bih, Whh, bhh, cur);
        logits_kernel<<<NVBLK, 128, SMEM_DYN>>>(bfc, out, t);
        argmax_embed_kernel<<<64, 128>>>(emb);
        cur = 1 - cur;
    }
}